// round 3
// baseline (speedup 1.0000x reference)
#include <cuda_runtime.h>
#include <cuda_bf16.h>

#define KEHALF_F 7.199822675975274f
#define MAX_ATOMS 500000

struct ZConsts {
    float spapow;   // sp(apow)
    float spadiv;   // sp(adiv)
    float s1, s2, s3, s4;       // sp(a_k)
    float c1n, c2n, c3n, c4n;   // KEHALF * sp(c_k)/csum
};

__device__ ZConsts g_consts;
__device__ float2 g_zz[MAX_ATOMS];   // {Zf, z=Zf^sp(apow)} packed per atom

__device__ __forceinline__ float softplus_acc(float x) {
    // accurate softplus for the one-time constants
    return (x > 20.f) ? x : log1pf(expf(x));
}

__global__ void consts_kernel(const float* adiv, const float* apow,
                              const float* c1, const float* c2,
                              const float* c3, const float* c4,
                              const float* a1, const float* a2,
                              const float* a3, const float* a4) {
    ZConsts C;
    C.spapow = softplus_acc(*apow);
    C.spadiv = softplus_acc(*adiv);
    C.s1 = softplus_acc(*a1);
    C.s2 = softplus_acc(*a2);
    C.s3 = softplus_acc(*a3);
    C.s4 = softplus_acc(*a4);
    float c1p = softplus_acc(*c1);
    float c2p = softplus_acc(*c2);
    float c3p = softplus_acc(*c3);
    float c4p = softplus_acc(*c4);
    float inv = KEHALF_F / (c1p + c2p + c3p + c4p);
    C.c1n = c1p * inv;
    C.c2n = c2p * inv;
    C.c3n = c3p * inv;
    C.c4n = c4p * inv;
    g_consts = C;
}

__global__ void atom_kernel(const float* __restrict__ Zf, float* __restrict__ out, int n) {
    int i = blockIdx.x * blockDim.x + threadIdx.x;
    if (i < n) {
        float Z = Zf[i];
        // Z >= 1 so __logf is safe; one-time per atom, precision ample
        float z = __expf(g_consts.spapow * __logf(Z));
        g_zz[i] = make_float2(Z, z);
        out[i] = 0.0f;   // d_out is poisoned; we own zero-init
    }
}

__device__ __forceinline__ void do_pair(float r, float cv, int i, int j,
                                        const ZConsts& C, float* __restrict__ out) {
    float2 zi = g_zz[i];
    float2 zj = g_zz[j];
    float a = (zi.y + zj.y) * C.spadiv;
    float t = a * r;
    float f = C.c1n * __expf(-C.s1 * t)
            + C.c2n * __expf(-C.s2 * t)
            + C.c3n * __expf(-C.s3 * t)
            + C.c4n * __expf(-C.s4 * t);
    float contrib = f * cv * zi.x * zj.x * __fdividef(1.0f, r);
    atomicAdd(out + i, contrib);
}

__global__ void __launch_bounds__(256)
pair_kernel4(const float4* __restrict__ rij, const float4* __restrict__ cut,
             const int4* __restrict__ ii, const int4* __restrict__ jj,
             float* __restrict__ out, int nq) {
    int t = blockIdx.x * blockDim.x + threadIdx.x;
    if (t >= nq) return;
    ZConsts C = g_consts;
    float4 r4 = rij[t];
    float4 c4 = cut[t];
    int4 i4 = ii[t];
    int4 j4 = jj[t];
    do_pair(r4.x, c4.x, i4.x, j4.x, C, out);
    do_pair(r4.y, c4.y, i4.y, j4.y, C, out);
    do_pair(r4.z, c4.z, i4.z, j4.z, C, out);
    do_pair(r4.w, c4.w, i4.w, j4.w, C, out);
}

__global__ void pair_kernel_tail(const float* __restrict__ rij, const float* __restrict__ cut,
                                 const int* __restrict__ ii, const int* __restrict__ jj,
                                 float* __restrict__ out, int start, int P) {
    int p = start + blockIdx.x * blockDim.x + threadIdx.x;
    if (p >= P) return;
    ZConsts C = g_consts;
    do_pair(rij[p], cut[p], ii[p], jj[p], C, out);
}

extern "C" void kernel_launch(void* const* d_in, const int* in_sizes, int n_in,
                              void* d_out, int out_size) {
    // metadata order: N, Zf, rij, cutoff_values, idx_i, idx_j,
    //                 adiv, apow, c1, c2, c3, c4, a1, a2, a3, a4
    const float* Zf   = (const float*)d_in[1];
    const float* rij  = (const float*)d_in[2];
    const float* cutv = (const float*)d_in[3];
    const int*   ii   = (const int*)d_in[4];
    const int*   jj   = (const int*)d_in[5];
    const float* adiv = (const float*)d_in[6];
    const float* apow = (const float*)d_in[7];
    const float* c1   = (const float*)d_in[8];
    const float* c2   = (const float*)d_in[9];
    const float* c3   = (const float*)d_in[10];
    const float* c4   = (const float*)d_in[11];
    const float* a1   = (const float*)d_in[12];
    const float* a2   = (const float*)d_in[13];
    const float* a3   = (const float*)d_in[14];
    const float* a4   = (const float*)d_in[15];
    float* out = (float*)d_out;

    int n_atoms = in_sizes[1];
    int P       = in_sizes[2];
    if (n_atoms > MAX_ATOMS) n_atoms = MAX_ATOMS;

    consts_kernel<<<1, 1>>>(adiv, apow, c1, c2, c3, c4, a1, a2, a3, a4);

    atom_kernel<<<(n_atoms + 255) / 256, 256>>>(Zf, out, n_atoms);

    int nq = P / 4;
    if (nq > 0) {
        pair_kernel4<<<(nq + 255) / 256, 256>>>(
            (const float4*)rij, (const float4*)cutv,
            (const int4*)ii, (const int4*)jj, out, nq);
    }
    int done = nq * 4;
    int rem = P - done;
    if (rem > 0) {
        pair_kernel_tail<<<(rem + 255) / 256, 256>>>(rij, cutv, ii, jj, out, done, P);
    }
}